// round 7
// baseline (speedup 1.0000x reference)
#include <cuda_runtime.h>
#include <cuda_bf16.h>
#include <math.h>

// ---------------------------------------------------------------------------
// Problem constants
//   D = 512, K = 8, S = 4, B = 8192, SCALE = D^-0.5, LN_EPS = 1e-5
// Dataflow:
//   Qw = workspace @ Wq_w^T                      (batch independent, [4,512])
//   Kw = hidden @ Wk_w^T ; Vw = hidden @ Wv_w^T ; Qr = hidden @ Wq_r^T
//   attn_w = softmax_k(mask(Qw . Kw * SCALE)) (nan->0)
//   ws_upd = LN(ws + attn_w @ Vw)
//   Kr = ws_upd @ Wk_r^T ; Vr = ws_upd @ Wv_r^T
//   attn_r = softmax_s(Qr . Kr * SCALE) ; bc = attn_r @ Vr
//   out = LN(hidden + bc @ Wo^T)
// ---------------------------------------------------------------------------

#define NB      8192
#define NK      8
#define NS      4
#define ND      512
#define NROWS   (NB*NK)      // 65536
#define NSROWS  (NB*NS)      // 32768
#define ATT_SCALE 0.044194173824159216f
#define LN_EPS  1e-5f

// ---------------- scratch (device globals; no allocations allowed) ---------
// Buffer reuse: sc_A holds Kw then BC; sc_B holds Vw then BCW.
__device__ float sc_A  [NROWS  * ND];   // 128 MB  (Kw -> BC)
__device__ float sc_B  [NROWS  * ND];   // 128 MB  (Vw -> BCW)
__device__ float sc_Qr [NROWS  * ND];   // 128 MB
__device__ float sc_WSU[NSROWS * ND];   //  64 MB
__device__ float sc_Kr [NSROWS * ND];   //  64 MB
__device__ float sc_Vr [NSROWS * ND];   //  64 MB
__device__ float sc_Qw [NS * ND];
__device__ unsigned char sc_mask[NB * NK];

// ---------------- packed f32x2 helpers -------------------------------------
typedef unsigned long long u64;

__device__ __forceinline__ u64 pk2(float x, float y) {
    u64 r; asm("mov.b64 %0,{%1,%2};" : "=l"(r) : "f"(x), "f"(y)); return r;
}
__device__ __forceinline__ void fma2(u64& c, u64 a, u64 b) {
    asm("fma.rn.f32x2 %0,%1,%2,%0;" : "+l"(c) : "l"(a), "l"(b));
}
__device__ __forceinline__ float2 upk(u64 v) {
    float2 f; asm("mov.b64 {%0,%1},%2;" : "=f"(f.x), "=f"(f.y) : "l"(v)); return f;
}

// ---------------------------------------------------------------------------
// Mask canonicalization.
// The harness may deliver the jax bool mask as uint8 (1B/elem) or int32
// (4B/elem). Detect on-device: under int32 encoding every byte at position
// p with p%4 != 0 is zero within the first NB*NK bytes (a valid read under
// BOTH interpretations); a genuine uint8 bool array with ~50% ones cannot
// satisfy that. Then write a canonical uint8 mask.
// ---------------------------------------------------------------------------
__global__ void __launch_bounds__(1024) mask_canon_kernel(
    const unsigned char* __restrict__ mraw)
{
    __shared__ int s_any;
    if (threadIdx.x == 0) s_any = 0;
    __syncthreads();

    int any = 0;
    for (int p = threadIdx.x; p < NB * NK; p += 1024)
        if ((p & 3) != 0 && mraw[p]) any = 1;
    if (any) atomicOr(&s_any, 1);
    __syncthreads();

    if (s_any) {
        // uint8 layout
        for (int i = threadIdx.x; i < NB * NK; i += 1024)
            sc_mask[i] = mraw[i] ? 1 : 0;
    } else {
        // int32 layout
        const int* mi = (const int*)mraw;
        for (int i = threadIdx.x; i < NB * NK; i += 1024)
            sc_mask[i] = mi[i] ? 1 : 0;
    }
}

// ---------------------------------------------------------------------------
// Generic GEMM: C[M,512] = A[M,512] * W[512,512]^T  (W row-major [out,in])
// Tile 128x128, BK=16, 256 threads, 8x8 per thread, FFMA2 inner loop.
// Grid: (M/128, 4)
// ---------------------------------------------------------------------------
__global__ void __launch_bounds__(256, 2) gemm512_xt(
    const float* __restrict__ A, const float* __restrict__ W,
    float* __restrict__ C)
{
    __shared__ float As[16][128];   // k-major
    __shared__ float Ws[16][128];   // k-major

    const int t   = threadIdx.x;
    const int ldr = t >> 2;          // 0..63 (row within tile, +64 for second)
    const int ldc = (t & 3) << 2;    // 0,4,8,12 (k offset within tile)
    const int tm8 = (t >> 4) << 3;   // output m sub-tile base (0..120)
    const int tn8 = (t & 15) << 3;   // output n sub-tile base (0..120)

    const float* Ab = A + ((size_t)blockIdx.x << 7) * ND;
    const float* Wb = W + ((size_t)blockIdx.y << 7) * ND;

    u64 acc[8][4];
#pragma unroll
    for (int i = 0; i < 8; i++)
#pragma unroll
        for (int j = 0; j < 4; j++) acc[i][j] = 0ull;

    float4 pa0, pa1, pw0, pw1;

    // prologue: load k-tile 0
    pa0 = *(const float4*)(Ab + (size_t)ldr * ND + ldc);
    pa1 = *(const float4*)(Ab + (size_t)(ldr + 64) * ND + ldc);
    pw0 = *(const float4*)(Wb + (size_t)ldr * ND + ldc);
    pw1 = *(const float4*)(Wb + (size_t)(ldr + 64) * ND + ldc);
    As[ldc + 0][ldr] = pa0.x; As[ldc + 1][ldr] = pa0.y;
    As[ldc + 2][ldr] = pa0.z; As[ldc + 3][ldr] = pa0.w;
    As[ldc + 0][ldr + 64] = pa1.x; As[ldc + 1][ldr + 64] = pa1.y;
    As[ldc + 2][ldr + 64] = pa1.z; As[ldc + 3][ldr + 64] = pa1.w;
    Ws[ldc + 0][ldr] = pw0.x; Ws[ldc + 1][ldr] = pw0.y;
    Ws[ldc + 2][ldr] = pw0.z; Ws[ldc + 3][ldr] = pw0.w;
    Ws[ldc + 0][ldr + 64] = pw1.x; Ws[ldc + 1][ldr + 64] = pw1.y;
    Ws[ldc + 2][ldr + 64] = pw1.z; Ws[ldc + 3][ldr + 64] = pw1.w;
    __syncthreads();

    for (int kt = 0; kt < 32; ++kt) {
        if (kt < 31) {
            const int kk = (kt + 1) * 16;
            pa0 = *(const float4*)(Ab + (size_t)ldr * ND + kk + ldc);
            pa1 = *(const float4*)(Ab + (size_t)(ldr + 64) * ND + kk + ldc);
            pw0 = *(const float4*)(Wb + (size_t)ldr * ND + kk + ldc);
            pw1 = *(const float4*)(Wb + (size_t)(ldr + 64) * ND + kk + ldc);
        }
#pragma unroll
        for (int k = 0; k < 16; ++k) {
            float4 b0 = *(const float4*)&Ws[k][tn8];
            float4 b1 = *(const float4*)&Ws[k][tn8 + 4];
            u64 bb0 = pk2(b0.x, b0.y), bb1 = pk2(b0.z, b0.w);
            u64 bb2 = pk2(b1.x, b1.y), bb3 = pk2(b1.z, b1.w);
            float4 a0 = *(const float4*)&As[k][tm8];
            float4 a1 = *(const float4*)&As[k][tm8 + 4];
            float av[8] = {a0.x, a0.y, a0.z, a0.w, a1.x, a1.y, a1.z, a1.w};
#pragma unroll
            for (int i = 0; i < 8; i++) {
                u64 aa = pk2(av[i], av[i]);
                fma2(acc[i][0], aa, bb0);
                fma2(acc[i][1], aa, bb1);
                fma2(acc[i][2], aa, bb2);
                fma2(acc[i][3], aa, bb3);
            }
        }
        __syncthreads();
        if (kt < 31) {
            As[ldc + 0][ldr] = pa0.x; As[ldc + 1][ldr] = pa0.y;
            As[ldc + 2][ldr] = pa0.z; As[ldc + 3][ldr] = pa0.w;
            As[ldc + 0][ldr + 64] = pa1.x; As[ldc + 1][ldr + 64] = pa1.y;
            As[ldc + 2][ldr + 64] = pa1.z; As[ldc + 3][ldr + 64] = pa1.w;
            Ws[ldc + 0][ldr] = pw0.x; Ws[ldc + 1][ldr] = pw0.y;
            Ws[ldc + 2][ldr] = pw0.z; Ws[ldc + 3][ldr] = pw0.w;
            Ws[ldc + 0][ldr + 64] = pw1.x; Ws[ldc + 1][ldr + 64] = pw1.y;
            Ws[ldc + 2][ldr + 64] = pw1.z; Ws[ldc + 3][ldr + 64] = pw1.w;
            __syncthreads();
        }
    }

    const size_t crow = ((size_t)blockIdx.x << 7) + tm8;
    const int    ccol = (blockIdx.y << 7) + tn8;
#pragma unroll
    for (int i = 0; i < 8; i++) {
        float2 c0 = upk(acc[i][0]), c1 = upk(acc[i][1]);
        float2 c2 = upk(acc[i][2]), c3 = upk(acc[i][3]);
        float4 o0 = make_float4(c0.x, c0.y, c1.x, c1.y);
        float4 o1 = make_float4(c2.x, c2.y, c3.x, c3.y);
        float* cp = C + (crow + i) * (size_t)ND + ccol;
        *(float4*)cp       = o0;
        *(float4*)(cp + 4) = o1;
    }
}

// ---------------------------------------------------------------------------
// Qw precompute: Qw[s,e] = sum_d workspace[s,d] * Wq_w[e,d]   (1 block, 512 thr)
// ---------------------------------------------------------------------------
__global__ void __launch_bounds__(512) qw_kernel(
    const float* __restrict__ workspace, const float* __restrict__ Wq_w)
{
    __shared__ float sW[NS][ND];
    const int tid = threadIdx.x;
    ((float4*)sW)[tid] = ((const float4*)workspace)[tid];  // 512 f4 = 2048 floats
    __syncthreads();

    const float4* wr = (const float4*)(Wq_w + (size_t)tid * ND);
    float a0 = 0.f, a1 = 0.f, a2 = 0.f, a3 = 0.f;
#pragma unroll 4
    for (int q = 0; q < 128; q++) {
        float4 w = wr[q];
        const int d = q * 4;
        a0 += sW[0][d]*w.x + sW[0][d+1]*w.y + sW[0][d+2]*w.z + sW[0][d+3]*w.w;
        a1 += sW[1][d]*w.x + sW[1][d+1]*w.y + sW[1][d+2]*w.z + sW[1][d+3]*w.w;
        a2 += sW[2][d]*w.x + sW[2][d+1]*w.y + sW[2][d+2]*w.z + sW[2][d+3]*w.w;
        a3 += sW[3][d]*w.x + sW[3][d+1]*w.y + sW[3][d+2]*w.z + sW[3][d+3]*w.w;
    }
    sc_Qw[0*ND + tid] = a0;
    sc_Qw[1*ND + tid] = a1;
    sc_Qw[2*ND + tid] = a2;
    sc_Qw[3*ND + tid] = a3;
}

// ---------------------------------------------------------------------------
// block-wide sum over 512 threads
// ---------------------------------------------------------------------------
__device__ __forceinline__ float blk_sum512(float v, float* red)
{
    const int lane = threadIdx.x & 31, warp = threadIdx.x >> 5;
#pragma unroll
    for (int o = 16; o; o >>= 1) v += __shfl_xor_sync(0xffffffffu, v, o);
    if (lane == 0) red[warp] = v;
    __syncthreads();
    if (warp == 0) {
        float t = (lane < 16) ? red[lane] : 0.f;
#pragma unroll
        for (int o = 8; o; o >>= 1) t += __shfl_xor_sync(0xffffffffu, t, o);
        if (lane == 0) red[16] = t;
    }
    __syncthreads();
    float r = red[16];
    __syncthreads();
    return r;
}

// ---------------------------------------------------------------------------
// Write attention + LN:  one block per b (512 threads)
// ---------------------------------------------------------------------------
__global__ void __launch_bounds__(512) attn_write_kernel(
    const float* __restrict__ Kw, const float* __restrict__ Vw,
    const float* __restrict__ workspace,
    const float* __restrict__ gw, const float* __restrict__ bw,
    float* __restrict__ WSU)
{
    const int b = blockIdx.x;
    const int tid = threadIdx.x;
    __shared__ float sKw[NK][ND];
    __shared__ float sVw[NK][ND];
    __shared__ float sP[NS][NK];
    __shared__ float red[17];

    const float4* k4 = (const float4*)(Kw + (size_t)b * NK * ND);
    const float4* v4 = (const float4*)(Vw + (size_t)b * NK * ND);
    ((float4*)sKw)[tid]       = k4[tid];
    ((float4*)sKw)[tid + 512] = k4[tid + 512];
    ((float4*)sVw)[tid]       = v4[tid];
    ((float4*)sVw)[tid + 512] = v4[tid + 512];
    __syncthreads();

    // logits: 32 (s,k) pairs over 16 warps (2 per warp)
    const int warp = tid >> 5, lane = tid & 31;
#pragma unroll
    for (int j = 0; j < 2; j++) {
        const int pair = warp * 2 + j;
        const int s = pair >> 3, k = pair & 7;
        float sum = 0.f;
#pragma unroll 4
        for (int i = lane; i < ND; i += 32) sum += sc_Qw[s * ND + i] * sKw[k][i];
#pragma unroll
        for (int o = 16; o; o >>= 1) sum += __shfl_xor_sync(0xffffffffu, sum, o);
        if (lane == 0) sP[s][k] = sum * ATT_SCALE;
    }
    __syncthreads();

    // masked softmax (+ nan->0 semantics for fully-masked rows)
    if (tid < NS) {
        const int s = tid;
        unsigned char mk[NK];
        float mx = -INFINITY;
#pragma unroll
        for (int k = 0; k < NK; k++) {
            mk[k] = sc_mask[b * NK + k];
            if (mk[k]) mx = fmaxf(mx, sP[s][k]);
        }
        float pv[NK], den = 0.f;
#pragma unroll
        for (int k = 0; k < NK; k++) {
            float e = mk[k] ? expf(sP[s][k] - mx) : 0.f;
            pv[k] = e; den += e;
        }
        const float inv = (den > 0.f) ? (1.f / den) : 0.f;
#pragma unroll
        for (int k = 0; k < NK; k++) sP[s][k] = pv[k] * inv;
    }
    __syncthreads();

    // ws_upd = LN(ws + P @ Vw)
    const float gv = gw[tid], bv = bw[tid];
#pragma unroll
    for (int s = 0; s < NS; s++) {
        float v = workspace[s * ND + tid];
#pragma unroll
        for (int k = 0; k < NK; k++) v += sP[s][k] * sVw[k][tid];
        const float mu = blk_sum512(v, red) * (1.f / 512.f);
        const float d = v - mu;
        const float var = blk_sum512(d * d, red) * (1.f / 512.f);
        WSU[((size_t)b * NS + s) * ND + tid] = d * rsqrtf(var + LN_EPS) * gv + bv;
    }
}

// ---------------------------------------------------------------------------
// Read attention: one block per b (512 threads); bc = softmax(Qr.Kr)*Vr
// ---------------------------------------------------------------------------
__global__ void __launch_bounds__(512) attn_read_kernel(
    const float* __restrict__ Qr, const float* __restrict__ Kr,
    const float* __restrict__ Vr, float* __restrict__ BC)
{
    const int b = blockIdx.x;
    const int tid = threadIdx.x;
    __shared__ float sQr[NK][ND];
    __shared__ float sKr[NS][ND];
    __shared__ float sVr[NS][ND];
    __shared__ float sP[NK][NS];

    const float4* q4 = (const float4*)(Qr + (size_t)b * NK * ND);
    ((float4*)sQr)[tid]       = q4[tid];
    ((float4*)sQr)[tid + 512] = q4[tid + 512];
    ((float4*)sKr)[tid] = ((const float4*)(Kr + (size_t)b * NS * ND))[tid];
    ((float4*)sVr)[tid] = ((const float4*)(Vr + (size_t)b * NS * ND))[tid];
    __syncthreads();

    const int warp = tid >> 5, lane = tid & 31;
#pragma unroll
    for (int j = 0; j < 2; j++) {
        const int pair = warp * 2 + j;
        const int k = pair >> 2, s = pair & 3;
        float sum = 0.f;
#pragma unroll 4
        for (int i = lane; i < ND; i += 32) sum += sQr[k][i] * sKr[s][i];
#pragma unroll
        for (int o = 16; o; o >>= 1) sum += __shfl_xor_sync(0xffffffffu, sum, o);
        if (lane == 0) sP[k][s] = sum * ATT_SCALE;
    }
    __syncthreads();

    if (tid < NK) {
        const int k = tid;
        float mx = -INFINITY;
#pragma unroll
        for (int s = 0; s < NS; s++) mx = fmaxf(mx, sP[k][s]);
        float pv[NS], den = 0.f;
#pragma unroll
        for (int s = 0; s < NS; s++) { pv[s] = expf(sP[k][s] - mx); den += pv[s]; }
        const float inv = 1.f / den;
#pragma unroll
        for (int s = 0; s < NS; s++) sP[k][s] = pv[s] * inv;
    }
    __syncthreads();

#pragma unroll
    for (int k = 0; k < NK; k++) {
        float v = 0.f;
#pragma unroll
        for (int s = 0; s < NS; s++) v += sP[k][s] * sVr[s][tid];
        BC[((size_t)b * NK + k) * ND + tid] = v;
    }
}

// ---------------------------------------------------------------------------
// Final LN: out = LN(hidden + BCW); one block per row (512 threads)
// ---------------------------------------------------------------------------
__global__ void __launch_bounds__(512) ln_out_kernel(
    const float* __restrict__ hidden, const float* __restrict__ BCW,
    const float* __restrict__ g, const float* __restrict__ bb,
    float* __restrict__ out)
{
    const size_t r = blockIdx.x;
    const int tid = threadIdx.x;
    __shared__ float red[17];
    const float v = hidden[r * ND + tid] + BCW[r * ND + tid];
    const float mu = blk_sum512(v, red) * (1.f / 512.f);
    const float d = v - mu;
    const float var = blk_sum512(d * d, red) * (1.f / 512.f);
    out[r * ND + tid] = d * rsqrtf(var + LN_EPS) * g[tid] + bb[tid];
}

// ---------------------------------------------------------------------------
// launch
// ---------------------------------------------------------------------------
extern "C" void kernel_launch(void* const* d_in, const int* in_sizes, int n_in,
                              void* d_out, int out_size)
{
    const float*         hidden    = (const float*)d_in[0];
    const unsigned char* mask_raw  = (const unsigned char*)d_in[1];
    const float*         workspace = (const float*)d_in[2];
    const float*         Wq_w      = (const float*)d_in[3];
    const float*         Wk_w      = (const float*)d_in[4];
    const float*         Wv_w      = (const float*)d_in[5];
    const float*         Wq_r      = (const float*)d_in[6];
    const float*         Wk_r      = (const float*)d_in[7];
    const float*         Wv_r      = (const float*)d_in[8];
    const float*         Wo        = (const float*)d_in[9];
    const float*         g_ws      = (const float*)d_in[10];
    const float*         b_ws      = (const float*)d_in[11];
    const float*         g_out     = (const float*)d_in[12];
    const float*         b_out     = (const float*)d_in[13];
    float*               out       = (float*)d_out;

    float *pA, *pB, *pQr, *pWSU, *pKr, *pVr;
    cudaGetSymbolAddress((void**)&pA,   sc_A);
    cudaGetSymbolAddress((void**)&pB,   sc_B);
    cudaGetSymbolAddress((void**)&pQr,  sc_Qr);
    cudaGetSymbolAddress((void**)&pWSU, sc_WSU);
    cudaGetSymbolAddress((void**)&pKr,  sc_Kr);
    cudaGetSymbolAddress((void**)&pVr,  sc_Vr);

    mask_canon_kernel<<<1, 1024>>>(mask_raw);
    qw_kernel<<<1, 512>>>(workspace, Wq_w);

    const dim3 gBig(NROWS / 128, 4);    // M = 65536
    const dim3 gSml(NSROWS / 128, 4);   // M = 32768

    gemm512_xt<<<gBig, 256>>>(hidden, Wk_w, pA);   // Kw
    gemm512_xt<<<gBig, 256>>>(hidden, Wv_w, pB);   // Vw
    gemm512_xt<<<gBig, 256>>>(hidden, Wq_r, pQr);  // Qr

    attn_write_kernel<<<NB, 512>>>(pA, pB, workspace, g_ws, b_ws, pWSU);

    gemm512_xt<<<gSml, 256>>>(pWSU, Wk_r, pKr);
    gemm512_xt<<<gSml, 256>>>(pWSU, Wv_r, pVr);

    attn_read_kernel<<<NB, 512>>>(pQr, pKr, pVr, pA);   // BC reuses sc_A

    gemm512_xt<<<gBig, 256>>>(pA, Wo, pB);              // BCW reuses sc_B

    ln_out_kernel<<<NROWS, 512>>>(hidden, pB, g_out, b_out, out);
}

// round 10
// speedup vs baseline: 2.0590x; 2.0590x over previous
#include <cuda_runtime.h>
#include <cuda_bf16.h>
#include <math.h>
#include <stdint.h>

// ---------------------------------------------------------------------------
// D = 512, K = 8, S = 4, B = 8192
// GEMMs on tensor cores via mma.sync (bf16, fp32 accum) with 3-term hi/lo
// split for ~fp32 accuracy. tcgen05 is NOT available (harness PTX target is
// sm_103 without the 'a' feature suffix). Attention + LN stay SIMT.
// ---------------------------------------------------------------------------

#define NB      8192
#define NK      8
#define NS      4
#define ND      512
#define NROWS   (NB*NK)      // 65536
#define NSROWS  (NB*NS)      // 32768
#define ATT_SCALE 0.044194173824159216f
#define LN_EPS  1e-5f

// ---------------- scratch (device globals) ---------------------------------
__device__ float sc_Kw [NROWS  * ND];   // Kw -> later BC
__device__ float sc_Vw [NROWS  * ND];   // Vw -> later BCW
__device__ float sc_Qr [NROWS  * ND];
__device__ float sc_WSU[NSROWS * ND];
__device__ float sc_Kr [NSROWS * ND];
__device__ float sc_Vr [NSROWS * ND];
__device__ float sc_Qw [NS * ND];
__device__ unsigned char sc_mask[NB * NK];

// bf16 hi/lo split buffers
__device__ __nv_bfloat16 sb_hHi[NROWS * ND];
__device__ __nv_bfloat16 sb_hLo[NROWS * ND];
__device__ __nv_bfloat16 sb_xHi[NROWS * ND];
__device__ __nv_bfloat16 sb_xLo[NROWS * ND];
__device__ __nv_bfloat16 sb_wHi[6 * ND * ND];
__device__ __nv_bfloat16 sb_wLo[6 * ND * ND];

// ---------------- helpers ---------------------------------------------------
__device__ __forceinline__ uint32_t s2u(const void* p) {
    uint32_t a;
    asm("{ .reg .u64 t; cvta.to.shared.u64 t, %1; cvt.u32.u64 %0, t; }"
        : "=r"(a) : "l"(p));
    return a;
}
#define SWZ(x) ((x) ^ (((x) >> 3) & 0x70))

__device__ __forceinline__ void ldm4(uint32_t* r, uint32_t addr) {
    asm volatile("ldmatrix.sync.aligned.m8n8.x4.shared.b16 {%0,%1,%2,%3},[%4];"
        : "=r"(r[0]), "=r"(r[1]), "=r"(r[2]), "=r"(r[3]) : "r"(addr));
}
__device__ __forceinline__ void mma16816(float* d, const uint32_t* a,
                                         const uint32_t* b) {
    asm volatile(
        "mma.sync.aligned.m16n8k16.row.col.f32.bf16.bf16.f32 "
        "{%0,%1,%2,%3},{%4,%5,%6,%7},{%8,%9},{%0,%1,%2,%3};"
        : "+f"(d[0]), "+f"(d[1]), "+f"(d[2]), "+f"(d[3])
        : "r"(a[0]), "r"(a[1]), "r"(a[2]), "r"(a[3]), "r"(b[0]), "r"(b[1]));
}

// ---------------------------------------------------------------------------
// Tensor-core GEMM: C[M,512] = (Ahi+Alo) . (Bhi+Blo)^T   (B = W [N,K] rowmaj)
// 3-term split: hi.hi + hi.lo + lo.hi, fp32 accumulation.
// Block tile 128x128, BK=64, 256 threads (8 warps, 4x2, warp tile 32x64).
// grid = (N/128 = 4, M/128); blockIdx.x = n-tile so co-resident blocks share A.
// Dynamic SMEM: 4 tiles x 16 KB = 64 KB (SW128 swizzled for ldmatrix).
// ---------------------------------------------------------------------------
#define GEMM_SMEM 65536

__global__ void __launch_bounds__(256, 2)
gemm512_mma(const __nv_bfloat16* __restrict__ Ahi,
            const __nv_bfloat16* __restrict__ Alo,
            const __nv_bfloat16* __restrict__ Bhi,
            const __nv_bfloat16* __restrict__ Blo,
            float* __restrict__ C)
{
    extern __shared__ __align__(1024) char smem[];
    const uint32_t sbase = s2u(smem);
    const uint32_t OAH = 0, OAL = 16384, OBH = 32768, OBL = 49152;

    const int tid  = threadIdx.x;
    const int lane = tid & 31;
    const int w    = tid >> 5;
    const int wm   = (w >> 1) * 32;      // warp m offset (0,32,64,96)
    const int wn   = (w & 1) * 64;       // warp n offset (0,64)

    // global load mapping: thread t -> row = t>>1, 64-byte half h = t&1
    const int lrow = tid >> 1;
    const int lhalf = tid & 1;
    const size_t gArow = (size_t)blockIdx.y * 128 + lrow;
    const size_t gBrow = (size_t)blockIdx.x * 128 + lrow;

    float c[2][8][4];
#pragma unroll
    for (int i = 0; i < 2; i++)
#pragma unroll
        for (int j = 0; j < 8; j++)
#pragma unroll
            for (int q = 0; q < 4; q++) c[i][j][q] = 0.f;

    // ldmatrix source addresses (tile-local, swizzled), per k16 step ks:
    //   A: row = wm + mt*16 + (lane&15), chunk = ks*2 + (lane>>4)
    //   B: row = wn + np*16 + (lane&7) + ((lane>>4)<<3), chunk = ks*2 + ((lane>>3)&1)
    const int arow_l = (lane & 15);
    const int akch   = (lane >> 4);            // 0/1
    const int brow_l = (lane & 7) + ((lane >> 4) << 3);
    const int bkch   = ((lane >> 3) & 1);

    for (int kc = 0; kc < 8; kc++) {
        // ---- stage tiles: 4 x uint4 per thread per tile -------------------
        const uint4* pAh = (const uint4*)(Ahi + gArow * ND + kc * 64 + lhalf * 32);
        const uint4* pAl = (const uint4*)(Alo + gArow * ND + kc * 64 + lhalf * 32);
        const uint4* pBh = (const uint4*)(Bhi + gBrow * ND + kc * 64 + lhalf * 32);
        const uint4* pBl = (const uint4*)(Blo + gBrow * ND + kc * 64 + lhalf * 32);
        uint4 vah[4], val[4], vbh[4], vbl[4];
#pragma unroll
        for (int i = 0; i < 4; i++) {
            vah[i] = pAh[i]; val[i] = pAl[i];
            vbh[i] = pBh[i]; vbl[i] = pBl[i];
        }
        if (kc) __syncthreads();    // previous compute done before overwrite
#pragma unroll
        for (int i = 0; i < 4; i++) {
            const uint32_t d = SWZ((uint32_t)lrow * 128 + (lhalf * 4 + i) * 16);
            *(uint4*)(smem + OAH + d) = vah[i];
            *(uint4*)(smem + OAL + d) = val[i];
            *(uint4*)(smem + OBH + d) = vbh[i];
            *(uint4*)(smem + OBL + d) = vbl[i];
        }
        __syncthreads();

        // ---- compute: 4 k16 sub-steps -------------------------------------
#pragma unroll
        for (int ks = 0; ks < 4; ks++) {
            uint32_t ah[2][4], al[2][4];
#pragma unroll
            for (int mt = 0; mt < 2; mt++) {
                const uint32_t raw = (uint32_t)(wm + mt * 16 + arow_l) * 128
                                   + (ks * 2 + akch) * 16;
                const uint32_t ad = SWZ(raw);
                ldm4(ah[mt], sbase + OAH + ad);
                ldm4(al[mt], sbase + OAL + ad);
            }
            uint32_t bf[8][2];
            // --- B hi: hi.hi and lo.hi ---
#pragma unroll
            for (int np = 0; np < 4; np++) {
                const uint32_t raw = (uint32_t)(wn + np * 16 + brow_l) * 128
                                   + (ks * 2 + bkch) * 16;
                uint32_t r[4];
                ldm4(r, sbase + OBH + SWZ(raw));
                bf[2*np][0] = r[0]; bf[2*np][1] = r[1];
                bf[2*np+1][0] = r[2]; bf[2*np+1][1] = r[3];
            }
#pragma unroll
            for (int mt = 0; mt < 2; mt++)
#pragma unroll
                for (int nt = 0; nt < 8; nt++) {
                    mma16816(c[mt][nt], ah[mt], bf[nt]);
                    mma16816(c[mt][nt], al[mt], bf[nt]);
                }
            // --- B lo: hi.lo ---
#pragma unroll
            for (int np = 0; np < 4; np++) {
                const uint32_t raw = (uint32_t)(wn + np * 16 + brow_l) * 128
                                   + (ks * 2 + bkch) * 16;
                uint32_t r[4];
                ldm4(r, sbase + OBL + SWZ(raw));
                bf[2*np][0] = r[0]; bf[2*np][1] = r[1];
                bf[2*np+1][0] = r[2]; bf[2*np+1][1] = r[3];
            }
#pragma unroll
            for (int mt = 0; mt < 2; mt++)
#pragma unroll
                for (int nt = 0; nt < 8; nt++)
                    mma16816(c[mt][nt], ah[mt], bf[nt]);
        }
    }

    // ---- epilogue ---------------------------------------------------------
    const int gid = lane >> 2, tig = lane & 3;
    const size_t crow0 = (size_t)blockIdx.y * 128 + wm;
    const int    ccol0 = blockIdx.x * 128 + wn;
#pragma unroll
    for (int mt = 0; mt < 2; mt++)
#pragma unroll
        for (int nt = 0; nt < 8; nt++) {
            float* p0 = C + (crow0 + mt * 16 + gid) * ND + ccol0 + nt * 8 + tig * 2;
            float* p1 = p0 + 8 * ND;
            *(float2*)p0 = make_float2(c[mt][nt][0], c[mt][nt][1]);
            *(float2*)p1 = make_float2(c[mt][nt][2], c[mt][nt][3]);
        }
}

// ---------------------------------------------------------------------------
// fp32 -> bf16 hi/lo split
// ---------------------------------------------------------------------------
__global__ void __launch_bounds__(256) split_kernel(
    const float4* __restrict__ x,
    __nv_bfloat162* __restrict__ hi, __nv_bfloat162* __restrict__ lo, int n4)
{
    const int i = blockIdx.x * 256 + threadIdx.x;
    if (i >= n4) return;
    const float4 v = x[i];
    __nv_bfloat16 h0 = __float2bfloat16(v.x), h1 = __float2bfloat16(v.y);
    __nv_bfloat16 h2 = __float2bfloat16(v.z), h3 = __float2bfloat16(v.w);
    __nv_bfloat16 l0 = __float2bfloat16(v.x - __bfloat162float(h0));
    __nv_bfloat16 l1 = __float2bfloat16(v.y - __bfloat162float(h1));
    __nv_bfloat16 l2 = __float2bfloat16(v.z - __bfloat162float(h2));
    __nv_bfloat16 l3 = __float2bfloat16(v.w - __bfloat162float(h3));
    __nv_bfloat162 a; a.x = h0; a.y = h1;
    __nv_bfloat162 b; b.x = h2; b.y = h3;
    __nv_bfloat162 cc; cc.x = l0; cc.y = l1;
    __nv_bfloat162 d; d.x = l2; d.y = l3;
    hi[2*i] = a; hi[2*i+1] = b;
    lo[2*i] = cc; lo[2*i+1] = d;
}

// ---------------------------------------------------------------------------
// Mask canonicalization (uint8 vs int32 bool layout, detected on-device)
// ---------------------------------------------------------------------------
__global__ void __launch_bounds__(1024) mask_canon_kernel(
    const unsigned char* __restrict__ mraw)
{
    __shared__ int s_any;
    if (threadIdx.x == 0) s_any = 0;
    __syncthreads();
    int any = 0;
    for (int p = threadIdx.x; p < NB * NK; p += 1024)
        if ((p & 3) != 0 && mraw[p]) any = 1;
    if (any) atomicOr(&s_any, 1);
    __syncthreads();
    if (s_any) {
        for (int i = threadIdx.x; i < NB * NK; i += 1024)
            sc_mask[i] = mraw[i] ? 1 : 0;
    } else {
        const int* mi = (const int*)mraw;
        for (int i = threadIdx.x; i < NB * NK; i += 1024)
            sc_mask[i] = mi[i] ? 1 : 0;
    }
}

// ---------------------------------------------------------------------------
// Qw precompute (fp32 exact)
// ---------------------------------------------------------------------------
__global__ void __launch_bounds__(512) qw_kernel(
    const float* __restrict__ workspace, const float* __restrict__ Wq_w)
{
    __shared__ float sW[NS][ND];
    const int tid = threadIdx.x;
    ((float4*)sW)[tid] = ((const float4*)workspace)[tid];
    __syncthreads();
    const float4* wr = (const float4*)(Wq_w + (size_t)tid * ND);
    float a0 = 0.f, a1 = 0.f, a2 = 0.f, a3 = 0.f;
#pragma unroll 4
    for (int q = 0; q < 128; q++) {
        float4 w = wr[q];
        const int d = q * 4;
        a0 += sW[0][d]*w.x + sW[0][d+1]*w.y + sW[0][d+2]*w.z + sW[0][d+3]*w.w;
        a1 += sW[1][d]*w.x + sW[1][d+1]*w.y + sW[1][d+2]*w.z + sW[1][d+3]*w.w;
        a2 += sW[2][d]*w.x + sW[2][d+1]*w.y + sW[2][d+2]*w.z + sW[2][d+3]*w.w;
        a3 += sW[3][d]*w.x + sW[3][d+1]*w.y + sW[3][d+2]*w.z + sW[3][d+3]*w.w;
    }
    sc_Qw[0*ND + tid] = a0;
    sc_Qw[1*ND + tid] = a1;
    sc_Qw[2*ND + tid] = a2;
    sc_Qw[3*ND + tid] = a3;
}

// ---------------------------------------------------------------------------
__device__ __forceinline__ float blk_sum512(float v, float* red)
{
    const int lane = threadIdx.x & 31, warp = threadIdx.x >> 5;
#pragma unroll
    for (int o = 16; o; o >>= 1) v += __shfl_xor_sync(0xffffffffu, v, o);
    if (lane == 0) red[warp] = v;
    __syncthreads();
    if (warp == 0) {
        float t = (lane < 16) ? red[lane] : 0.f;
#pragma unroll
        for (int o = 8; o; o >>= 1) t += __shfl_xor_sync(0xffffffffu, t, o);
        if (lane == 0) red[16] = t;
    }
    __syncthreads();
    float r = red[16];
    __syncthreads();
    return r;
}

// ---------------------------------------------------------------------------
// Write attention + LN: one block per b (512 threads)
// ---------------------------------------------------------------------------
__global__ void __launch_bounds__(512) attn_write_kernel(
    const float* __restrict__ Kw, const float* __restrict__ Vw,
    const float* __restrict__ workspace,
    const float* __restrict__ gw, const float* __restrict__ bw,
    float* __restrict__ WSU)
{
    const int b = blockIdx.x;
    const int tid = threadIdx.x;
    __shared__ float sKw[NK][ND];
    __shared__ float sVw[NK][ND];
    __shared__ float sP[NS][NK];
    __shared__ float red[17];

    const float4* k4 = (const float4*)(Kw + (size_t)b * NK * ND);
    const float4* v4 = (const float4*)(Vw + (size_t)b * NK * ND);
    ((float4*)sKw)[tid]       = k4[tid];
    ((float4*)sKw)[tid + 512] = k4[tid + 512];
    ((float4*)sVw)[tid]       = v4[tid];
    ((float4*)sVw)[tid + 512] = v4[tid + 512];
    __syncthreads();

    const int warp = tid >> 5, lane = tid & 31;
#pragma unroll
    for (int j = 0; j < 2; j++) {
        const int pair = warp * 2 + j;
        const int s = pair >> 3, k = pair & 7;
        float sum = 0.f;
#pragma unroll 4
        for (int i = lane; i < ND; i += 32) sum += sc_Qw[s * ND + i] * sKw[k][i];
#pragma unroll
        for (int o = 16; o; o >>= 1) sum += __shfl_xor_sync(0xffffffffu, sum, o);
        if (lane == 0) sP[s][k] = sum * ATT_SCALE;
    }
    __syncthreads();

    if (tid < NS) {
        const int s = tid;
        unsigned char mk[NK];
        float mx = -INFINITY;
#pragma unroll
        for (int k = 0; k < NK; k++) {
            mk[k] = sc_mask[b * NK + k];
            if (mk[k]) mx = fmaxf(mx, sP[s][k]);
        }
        float pv[NK], den = 0.f;
#pragma unroll
        for (int k = 0; k < NK; k++) {
            float e = mk[k] ? expf(sP[s][k] - mx) : 0.f;
            pv[k] = e; den += e;
        }
        const float inv = (den > 0.f) ? (1.f / den) : 0.f;
#pragma unroll
        for (int k = 0; k < NK; k++) sP[s][k] = pv[k] * inv;
    }
    __syncthreads();

    const float gv = gw[tid], bv = bw[tid];
#pragma unroll
    for (int s = 0; s < NS; s++) {
        float v = workspace[s * ND + tid];
#pragma unroll
        for (int k = 0; k < NK; k++) v += sP[s][k] * sVw[k][tid];
        const float mu = blk_sum512(v, red) * (1.f / 512.f);
        const float d = v - mu;
        const float var = blk_sum512(d * d, red) * (1.f / 512.f);
        WSU[((size_t)b * NS + s) * ND + tid] = d * rsqrtf(var + LN_EPS) * gv + bv;
    }
}

// ---------------------------------------------------------------------------
// Read attention: one block per b (512 threads)
// ---------------------------------------------------------------------------
__global__ void __launch_bounds__(512) attn_read_kernel(
    const float* __restrict__ Qr, const float* __restrict__ Kr,
    const float* __restrict__ Vr, float* __restrict__ BC)
{
    const int b = blockIdx.x;
    const int tid = threadIdx.x;
    __shared__ float sQr[NK][ND];
    __shared__ float sKr[NS][ND];
    __shared__ float sVr[NS][ND];
    __shared__ float sP[NK][NS];

    const float4* q4 = (const float4*)(Qr + (size_t)b * NK * ND);
    ((float4*)sQr)[tid]       = q4[tid];
    ((float4*)sQr)[tid + 512] = q4[tid + 512];
    ((float4*)sKr)[tid] = ((const float4*)(Kr + (size_t)b * NS * ND))[tid];
    ((float4*)sVr)[tid] = ((const float4*)(Vr + (size_t)b * NS * ND))[tid];
    __syncthreads();

    const int warp = tid >> 5, lane = tid & 31;
#pragma unroll
    for (int j = 0; j < 2; j++) {
        const int pair = warp * 2 + j;
        const int k = pair >> 2, s = pair & 3;
        float sum = 0.f;
#pragma unroll 4
        for (int i = lane; i < ND; i += 32) sum += sQr[k][i] * sKr[s][i];
#pragma unroll
        for (int o = 16; o; o >>= 1) sum += __shfl_xor_sync(0xffffffffu, sum, o);
        if (lane == 0) sP[k][s] = sum * ATT_SCALE;
    }
    __syncthreads();

    if (tid < NK) {
        const int k = tid;
        float mx = -INFINITY;
#pragma unroll
        for (int s = 0; s < NS; s++) mx = fmaxf(mx, sP[k][s]);
        float pv[NS], den = 0.f;
#pragma unroll
        for (int s = 0; s < NS; s++) { pv[s] = expf(sP[k][s] - mx); den += pv[s]; }
        const float inv = 1.f / den;
#pragma unroll
        for (int s = 0; s < NS; s++) sP[k][s] = pv[s] * inv;
    }
    __syncthreads();

#pragma unroll
    for (int k = 0; k < NK; k++) {
        float v = 0.f;
#pragma unroll
        for (int s = 0; s < NS; s++) v += sP[k][s] * sVr[s][tid];
        BC[((size_t)b * NK + k) * ND + tid] = v;
    }
}

// ---------------------------------------------------------------------------
// Final LN
// ---------------------------------------------------------------------------
__global__ void __launch_bounds__(512) ln_out_kernel(
    const float* __restrict__ hidden, const float* __restrict__ BCW,
    const float* __restrict__ g, const float* __restrict__ bb,
    float* __restrict__ out)
{
    const size_t r = blockIdx.x;
    const int tid = threadIdx.x;
    __shared__ float red[17];
    const float v = hidden[r * ND + tid] + BCW[r * ND + tid];
    const float mu = blk_sum512(v, red) * (1.f / 512.f);
    const float d = v - mu;
    const float var = blk_sum512(d * d, red) * (1.f / 512.f);
    out[r * ND + tid] = d * rsqrtf(var + LN_EPS) * g[tid] + bb[tid];
}

// ---------------------------------------------------------------------------
// launch
// ---------------------------------------------------------------------------
extern "C" void kernel_launch(void* const* d_in, const int* in_sizes, int n_in,
                              void* d_out, int out_size)
{
    const float*         hidden    = (const float*)d_in[0];
    const unsigned char* mask_raw  = (const unsigned char*)d_in[1];
    const float*         workspace = (const float*)d_in[2];
    const float*         Wq_w      = (const float*)d_in[3];
    const float*         Wk_w      = (const float*)d_in[4];
    const float*         Wv_w      = (const float*)d_in[5];
    const float*         Wq_r      = (const float*)d_in[6];
    const float*         Wk_r      = (const float*)d_in[7];
    const float*         Wv_r      = (const float*)d_in[8];
    const float*         Wo        = (const float*)d_in[9];
    const float*         g_ws      = (const float*)d_in[10];
    const float*         b_ws      = (const float*)d_in[11];
    const float*         g_out     = (const float*)d_in[12];
    const float*         b_out     = (const float*)d_in[13];
    float*               out       = (float*)d_out;

    float *pKw, *pVw, *pQr, *pWSU, *pKr, *pVr;
    cudaGetSymbolAddress((void**)&pKw,  sc_Kw);
    cudaGetSymbolAddress((void**)&pVw,  sc_Vw);
    cudaGetSymbolAddress((void**)&pQr,  sc_Qr);
    cudaGetSymbolAddress((void**)&pWSU, sc_WSU);
    cudaGetSymbolAddress((void**)&pKr,  sc_Kr);
    cudaGetSymbolAddress((void**)&pVr,  sc_Vr);

    __nv_bfloat16 *hHi, *hLo, *xHi, *xLo, *wHi, *wLo;
    cudaGetSymbolAddress((void**)&hHi, sb_hHi);
    cudaGetSymbolAddress((void**)&hLo, sb_hLo);
    cudaGetSymbolAddress((void**)&xHi, sb_xHi);
    cudaGetSymbolAddress((void**)&xLo, sb_xLo);
    cudaGetSymbolAddress((void**)&wHi, sb_wHi);
    cudaGetSymbolAddress((void**)&wLo, sb_wLo);

    static int smem_set = 0;
    if (!smem_set) {
        cudaFuncSetAttribute(gemm512_mma,
                             cudaFuncAttributeMaxDynamicSharedMemorySize, GEMM_SMEM);
        smem_set = 1;
    }

    mask_canon_kernel<<<1, 1024>>>(mask_raw);
    qw_kernel<<<1, 512>>>(workspace, Wq_w);

    const int n4_big = NROWS * ND / 4;
    const int n4_sml = NSROWS * ND / 4;
    const int n4_w   = ND * ND / 4;
    const size_t WSZ = (size_t)ND * ND;

    split_kernel<<<(n4_big + 255) / 256, 256>>>(
        (const float4*)hidden, (__nv_bfloat162*)hHi, (__nv_bfloat162*)hLo, n4_big);

    const float* wsrc[6] = {Wk_w, Wv_w, Wq_r, Wk_r, Wv_r, Wo};
    for (int w = 0; w < 6; w++)
        split_kernel<<<(n4_w + 255) / 256, 256>>>(
            (const float4*)wsrc[w],
            (__nv_bfloat162*)(wHi + w * WSZ), (__nv_bfloat162*)(wLo + w * WSZ), n4_w);

    const dim3 gBig(4, NROWS / 128);   // (n-tiles, m-tiles) = (4, 512)
    const dim3 gSml(4, NSROWS / 128);  // (4, 256)

    gemm512_mma<<<gBig, 256, GEMM_SMEM>>>(hHi, hLo, wHi + 0*WSZ, wLo + 0*WSZ, pKw);
    gemm512_mma<<<gBig, 256, GEMM_SMEM>>>(hHi, hLo, wHi + 1*WSZ, wLo + 1*WSZ, pVw);
    gemm512_mma<<<gBig, 256, GEMM_SMEM>>>(hHi, hLo, wHi + 2*WSZ, wLo + 2*WSZ, pQr);

    attn_write_kernel<<<NB, 512>>>(pKw, pVw, workspace, g_ws, b_ws, pWSU);

    split_kernel<<<(n4_sml + 255) / 256, 256>>>(
        (const float4*)pWSU, (__nv_bfloat162*)xHi, (__nv_bfloat162*)xLo, n4_sml);

    gemm512_mma<<<gSml, 256, GEMM_SMEM>>>(xHi, xLo, wHi + 3*WSZ, wLo + 3*WSZ, pKr);
    gemm512_mma<<<gSml, 256, GEMM_SMEM>>>(xHi, xLo, wHi + 4*WSZ, wLo + 4*WSZ, pVr);

    attn_read_kernel<<<NB, 512>>>(pQr, pKr, pVr, pKw);          // BC -> sc_Kw

    split_kernel<<<(n4_big + 255) / 256, 256>>>(
        (const float4*)pKw, (__nv_bfloat162*)xHi, (__nv_bfloat162*)xLo, n4_big);

    gemm512_mma<<<gBig, 256, GEMM_SMEM>>>(xHi, xLo, wHi + 5*WSZ, wLo + 5*WSZ, pVw);  // BCW

    ln_out_kernel<<<NROWS, 512>>>(hidden, pVw, g_out, b_out, out);
}

// round 11
// speedup vs baseline: 2.5475x; 1.2373x over previous
#include <cuda_runtime.h>
#include <cuda_bf16.h>
#include <math.h>
#include <stdint.h>

// ---------------------------------------------------------------------------
// D = 512, K = 8, S = 4, B = 8192
// GEMMs on tensor cores via mma.sync (bf16, fp32 accum), 3-term hi/lo split.
// cp.async double-buffered pipeline, BK=32, 2 CTAs/SM.
// hi/lo splits of WSU and BC are fused into the attention kernel epilogues.
// ---------------------------------------------------------------------------

#define NB      8192
#define NK      8
#define NS      4
#define ND      512
#define NROWS   (NB*NK)      // 65536
#define NSROWS  (NB*NS)      // 32768
#define ATT_SCALE 0.044194173824159216f
#define LN_EPS  1e-5f

// ---------------- scratch (device globals) ---------------------------------
__device__ float sc_Kw [NROWS  * ND];
__device__ float sc_Vw [NROWS  * ND];   // Vw -> later BCW
__device__ float sc_Qr [NROWS  * ND];
__device__ float sc_Kr [NSROWS * ND];
__device__ float sc_Vr [NSROWS * ND];
__device__ float sc_Qw [NS * ND];
__device__ unsigned char sc_mask[NB * NK];

// bf16 hi/lo split buffers
__device__ __nv_bfloat16 sb_hHi[NROWS * ND];    // hidden
__device__ __nv_bfloat16 sb_hLo[NROWS * ND];
__device__ __nv_bfloat16 sb_xHi[NROWS * ND];    // WSU (first NSROWS) then BC
__device__ __nv_bfloat16 sb_xLo[NROWS * ND];
__device__ __nv_bfloat16 sb_wHi[6 * ND * ND];
__device__ __nv_bfloat16 sb_wLo[6 * ND * ND];

// ---------------- helpers ---------------------------------------------------
__device__ __forceinline__ uint32_t s2u(const void* p) {
    uint32_t a;
    asm("{ .reg .u64 t; cvta.to.shared.u64 t, %1; cvt.u32.u64 %0, t; }"
        : "=r"(a) : "l"(p));
    return a;
}
// 64-byte-row swizzle: chunk' = chunk ^ ((row>>1)&3)
#define SWZ32(x) ((x) ^ (((x) >> 3) & 0x30))

__device__ __forceinline__ void cpa16(uint32_t dst, const void* src) {
    asm volatile("cp.async.cg.shared.global [%0],[%1],16;"
                 :: "r"(dst), "l"(src) : "memory");
}
__device__ __forceinline__ void ldm4(uint32_t* r, uint32_t addr) {
    asm volatile("ldmatrix.sync.aligned.m8n8.x4.shared.b16 {%0,%1,%2,%3},[%4];"
        : "=r"(r[0]), "=r"(r[1]), "=r"(r[2]), "=r"(r[3]) : "r"(addr));
}
__device__ __forceinline__ void mma16816(float* d, const uint32_t* a,
                                         const uint32_t* b) {
    asm volatile(
        "mma.sync.aligned.m16n8k16.row.col.f32.bf16.bf16.f32 "
        "{%0,%1,%2,%3},{%4,%5,%6,%7},{%8,%9},{%0,%1,%2,%3};"
        : "+f"(d[0]), "+f"(d[1]), "+f"(d[2]), "+f"(d[3])
        : "r"(a[0]), "r"(a[1]), "r"(a[2]), "r"(a[3]), "r"(b[0]), "r"(b[1]));
}

// ---------------------------------------------------------------------------
// Tensor-core GEMM: C[M,512] = (Ahi+Alo) . (Bhi+Blo)^T   (B = W [N,K] rowmaj)
// 3-term: hi.hi + hi.lo + lo.hi, fp32 accumulation.
// Block tile 128x128, BK=32, 256 threads (8 warps 4x2, warp tile 32x64).
// 2-stage cp.async pipeline. SMEM: 2 x 4 x 8KB = 64KB. 2 CTAs/SM.
// grid = (4 n-tiles, M/128).
// ---------------------------------------------------------------------------
#define GEMM_SMEM 65536
// per-stage tile offsets
#define T_AH 0
#define T_AL 8192
#define T_BH 16384
#define T_BL 24576

#define LOAD_STAGE(kc, st) do {                                               \
    const uint32_t sb_ = sbase + (st) * 32768;                                \
    _Pragma("unroll")                                                         \
    for (int i_ = 0; i_ < 2; i_++) {                                          \
        const int row_ = (tid >> 2) + i_ * 64;                                \
        const int ch_  = tid & 3;                                             \
        const uint32_t doff_ = SWZ32((uint32_t)row_ * 64 + ch_ * 16);         \
        const size_t geA_ = gA + (size_t)row_ * ND + (kc) * 32 + ch_ * 8;     \
        const size_t geB_ = gB + (size_t)row_ * ND + (kc) * 32 + ch_ * 8;     \
        cpa16(sb_ + T_AH + doff_, Ahi + geA_);                                \
        cpa16(sb_ + T_AL + doff_, Alo + geA_);                                \
        cpa16(sb_ + T_BH + doff_, Bhi + geB_);                                \
        cpa16(sb_ + T_BL + doff_, Blo + geB_);                                \
    }                                                                         \
    asm volatile("cp.async.commit_group;" ::: "memory");                      \
} while (0)

__global__ void __launch_bounds__(256, 2)
gemm512_mma(const __nv_bfloat16* __restrict__ Ahi,
            const __nv_bfloat16* __restrict__ Alo,
            const __nv_bfloat16* __restrict__ Bhi,
            const __nv_bfloat16* __restrict__ Blo,
            float* __restrict__ C)
{
    extern __shared__ __align__(1024) char smem[];
    const uint32_t sbase = s2u(smem);

    const int tid  = threadIdx.x;
    const int lane = tid & 31;
    const int w    = tid >> 5;
    const int wm   = (w >> 1) * 32;      // warp m offset
    const int wn   = (w & 1) * 64;       // warp n offset

    const size_t gA = ((size_t)blockIdx.y * 128) * ND;
    const size_t gB = ((size_t)blockIdx.x * 128) * ND;

    float c[2][8][4];
#pragma unroll
    for (int i = 0; i < 2; i++)
#pragma unroll
        for (int j = 0; j < 8; j++)
#pragma unroll
            for (int q = 0; q < 4; q++) c[i][j][q] = 0.f;

    // precomputed tile-local ldmatrix offsets
    const int arow_l = lane & 15;
    const int akch   = lane >> 4;
    const int brow_l = (lane & 7) + ((lane >> 4) << 3);
    const int bkch   = (lane >> 3) & 1;

    uint32_t aoff[2][2];   // [ks][mt]
    uint32_t boff[2][4];   // [ks][np]
#pragma unroll
    for (int ks = 0; ks < 2; ks++) {
#pragma unroll
        for (int mt = 0; mt < 2; mt++)
            aoff[ks][mt] = SWZ32((uint32_t)(wm + mt * 16 + arow_l) * 64
                                 + (ks * 2 + akch) * 16);
#pragma unroll
        for (int np = 0; np < 4; np++)
            boff[ks][np] = SWZ32((uint32_t)(wn + np * 16 + brow_l) * 64
                                 + (ks * 2 + bkch) * 16);
    }

    LOAD_STAGE(0, 0);

#pragma unroll 1
    for (int kc = 0; kc < 16; kc++) {
        asm volatile("cp.async.wait_group 0;" ::: "memory");
        __syncthreads();
        if (kc < 15) LOAD_STAGE(kc + 1, (kc + 1) & 1);

        const uint32_t sst = sbase + (kc & 1) * 32768;
#pragma unroll
        for (int ks = 0; ks < 2; ks++) {
            uint32_t ah[2][4], al[2][4];
#pragma unroll
            for (int mt = 0; mt < 2; mt++) {
                ldm4(ah[mt], sst + T_AH + aoff[ks][mt]);
                ldm4(al[mt], sst + T_AL + aoff[ks][mt]);
            }
            uint32_t bf[8][2];
#pragma unroll
            for (int np = 0; np < 4; np++) {
                uint32_t r[4];
                ldm4(r, sst + T_BH + boff[ks][np]);
                bf[2*np][0] = r[0]; bf[2*np][1] = r[1];
                bf[2*np+1][0] = r[2]; bf[2*np+1][1] = r[3];
            }
#pragma unroll
            for (int mt = 0; mt < 2; mt++)
#pragma unroll
                for (int nt = 0; nt < 8; nt++) {
                    mma16816(c[mt][nt], ah[mt], bf[nt]);   // hi.hi
                    mma16816(c[mt][nt], al[mt], bf[nt]);   // lo.hi
                }
#pragma unroll
            for (int np = 0; np < 4; np++) {
                uint32_t r[4];
                ldm4(r, sst + T_BL + boff[ks][np]);
                bf[2*np][0] = r[0]; bf[2*np][1] = r[1];
                bf[2*np+1][0] = r[2]; bf[2*np+1][1] = r[3];
            }
#pragma unroll
            for (int mt = 0; mt < 2; mt++)
#pragma unroll
                for (int nt = 0; nt < 8; nt++)
                    mma16816(c[mt][nt], ah[mt], bf[nt]);   // hi.lo
        }
    }

    // ---- epilogue ---------------------------------------------------------
    const int gid = lane >> 2, tig = lane & 3;
    const size_t crow0 = (size_t)blockIdx.y * 128 + wm;
    const int    ccol0 = blockIdx.x * 128 + wn;
#pragma unroll
    for (int mt = 0; mt < 2; mt++)
#pragma unroll
        for (int nt = 0; nt < 8; nt++) {
            float* p0 = C + (crow0 + mt * 16 + gid) * ND + ccol0 + nt * 8 + tig * 2;
            float* p1 = p0 + 8 * ND;
            *(float2*)p0 = make_float2(c[mt][nt][0], c[mt][nt][1]);
            *(float2*)p1 = make_float2(c[mt][nt][2], c[mt][nt][3]);
        }
}

// ---------------------------------------------------------------------------
// fp32 -> bf16 hi/lo split (hidden + weights only)
// ---------------------------------------------------------------------------
__global__ void __launch_bounds__(256) split_kernel(
    const float4* __restrict__ x,
    __nv_bfloat162* __restrict__ hi, __nv_bfloat162* __restrict__ lo, int n4)
{
    const int i = blockIdx.x * 256 + threadIdx.x;
    if (i >= n4) return;
    const float4 v = x[i];
    __nv_bfloat16 h0 = __float2bfloat16(v.x), h1 = __float2bfloat16(v.y);
    __nv_bfloat16 h2 = __float2bfloat16(v.z), h3 = __float2bfloat16(v.w);
    __nv_bfloat16 l0 = __float2bfloat16(v.x - __bfloat162float(h0));
    __nv_bfloat16 l1 = __float2bfloat16(v.y - __bfloat162float(h1));
    __nv_bfloat16 l2 = __float2bfloat16(v.z - __bfloat162float(h2));
    __nv_bfloat16 l3 = __float2bfloat16(v.w - __bfloat162float(h3));
    __nv_bfloat162 a; a.x = h0; a.y = h1;
    __nv_bfloat162 b; b.x = h2; b.y = h3;
    __nv_bfloat162 cc; cc.x = l0; cc.y = l1;
    __nv_bfloat162 d; d.x = l2; d.y = l3;
    hi[2*i] = a; hi[2*i+1] = b;
    lo[2*i] = cc; lo[2*i+1] = d;
}

// ---------------------------------------------------------------------------
// Mask canonicalization (uint8 vs int32 bool layout, detected on-device)
// ---------------------------------------------------------------------------
__global__ void __launch_bounds__(1024) mask_canon_kernel(
    const unsigned char* __restrict__ mraw)
{
    __shared__ int s_any;
    if (threadIdx.x == 0) s_any = 0;
    __syncthreads();
    int any = 0;
    for (int p = threadIdx.x; p < NB * NK; p += 1024)
        if ((p & 3) != 0 && mraw[p]) any = 1;
    if (any) atomicOr(&s_any, 1);
    __syncthreads();
    if (s_any) {
        for (int i = threadIdx.x; i < NB * NK; i += 1024)
            sc_mask[i] = mraw[i] ? 1 : 0;
    } else {
        const int* mi = (const int*)mraw;
        for (int i = threadIdx.x; i < NB * NK; i += 1024)
            sc_mask[i] = mi[i] ? 1 : 0;
    }
}

// ---------------------------------------------------------------------------
// Qw precompute (fp32 exact)
// ---------------------------------------------------------------------------
__global__ void __launch_bounds__(512) qw_kernel(
    const float* __restrict__ workspace, const float* __restrict__ Wq_w)
{
    __shared__ float sW[NS][ND];
    const int tid = threadIdx.x;
    ((float4*)sW)[tid] = ((const float4*)workspace)[tid];
    __syncthreads();
    const float4* wr = (const float4*)(Wq_w + (size_t)tid * ND);
    float a0 = 0.f, a1 = 0.f, a2 = 0.f, a3 = 0.f;
#pragma unroll 4
    for (int q = 0; q < 128; q++) {
        float4 w = wr[q];
        const int d = q * 4;
        a0 += sW[0][d]*w.x + sW[0][d+1]*w.y + sW[0][d+2]*w.z + sW[0][d+3]*w.w;
        a1 += sW[1][d]*w.x + sW[1][d+1]*w.y + sW[1][d+2]*w.z + sW[1][d+3]*w.w;
        a2 += sW[2][d]*w.x + sW[2][d+1]*w.y + sW[2][d+2]*w.z + sW[2][d+3]*w.w;
        a3 += sW[3][d]*w.x + sW[3][d+1]*w.y + sW[3][d+2]*w.z + sW[3][d+3]*w.w;
    }
    sc_Qw[0*ND + tid] = a0;
    sc_Qw[1*ND + tid] = a1;
    sc_Qw[2*ND + tid] = a2;
    sc_Qw[3*ND + tid] = a3;
}

// ---------------------------------------------------------------------------
__device__ __forceinline__ float blk_sum512(float v, float* red)
{
    const int lane = threadIdx.x & 31, warp = threadIdx.x >> 5;
#pragma unroll
    for (int o = 16; o; o >>= 1) v += __shfl_xor_sync(0xffffffffu, v, o);
    if (lane == 0) red[warp] = v;
    __syncthreads();
    if (warp == 0) {
        float t = (lane < 16) ? red[lane] : 0.f;
#pragma unroll
        for (int o = 8; o; o >>= 1) t += __shfl_xor_sync(0xffffffffu, t, o);
        if (lane == 0) red[16] = t;
    }
    __syncthreads();
    float r = red[16];
    __syncthreads();
    return r;
}

// ---------------------------------------------------------------------------
// Write attention + LN, emitting WSU directly as bf16 hi/lo
// ---------------------------------------------------------------------------
__global__ void __launch_bounds__(512) attn_write_kernel(
    const float* __restrict__ Kw, const float* __restrict__ Vw,
    const float* __restrict__ workspace,
    const float* __restrict__ gw, const float* __restrict__ bw,
    __nv_bfloat16* __restrict__ Whi, __nv_bfloat16* __restrict__ Wlo)
{
    const int b = blockIdx.x;
    const int tid = threadIdx.x;
    __shared__ float sKw[NK][ND];
    __shared__ float sVw[NK][ND];
    __shared__ float sP[NS][NK];
    __shared__ float red[17];

    const float4* k4 = (const float4*)(Kw + (size_t)b * NK * ND);
    const float4* v4 = (const float4*)(Vw + (size_t)b * NK * ND);
    ((float4*)sKw)[tid]       = k4[tid];
    ((float4*)sKw)[tid + 512] = k4[tid + 512];
    ((float4*)sVw)[tid]       = v4[tid];
    ((float4*)sVw)[tid + 512] = v4[tid + 512];
    __syncthreads();

    const int warp = tid >> 5, lane = tid & 31;
#pragma unroll
    for (int j = 0; j < 2; j++) {
        const int pair = warp * 2 + j;
        const int s = pair >> 3, k = pair & 7;
        float sum = 0.f;
#pragma unroll 4
        for (int i = lane; i < ND; i += 32) sum += sc_Qw[s * ND + i] * sKw[k][i];
#pragma unroll
        for (int o = 16; o; o >>= 1) sum += __shfl_xor_sync(0xffffffffu, sum, o);
        if (lane == 0) sP[s][k] = sum * ATT_SCALE;
    }
    __syncthreads();

    if (tid < NS) {
        const int s = tid;
        unsigned char mk[NK];
        float mx = -INFINITY;
#pragma unroll
        for (int k = 0; k < NK; k++) {
            mk[k] = sc_mask[b * NK + k];
            if (mk[k]) mx = fmaxf(mx, sP[s][k]);
        }
        float pv[NK], den = 0.f;
#pragma unroll
        for (int k = 0; k < NK; k++) {
            float e = mk[k] ? expf(sP[s][k] - mx) : 0.f;
            pv[k] = e; den += e;
        }
        const float inv = (den > 0.f) ? (1.f / den) : 0.f;
#pragma unroll
        for (int k = 0; k < NK; k++) sP[s][k] = pv[k] * inv;
    }
    __syncthreads();

    const float gv = gw[tid], bv = bw[tid];
#pragma unroll
    for (int s = 0; s < NS; s++) {
        float v = workspace[s * ND + tid];
#pragma unroll
        for (int k = 0; k < NK; k++) v += sP[s][k] * sVw[k][tid];
        const float mu = blk_sum512(v, red) * (1.f / 512.f);
        const float d = v - mu;
        const float var = blk_sum512(d * d, red) * (1.f / 512.f);
        const float o = d * rsqrtf(var + LN_EPS) * gv + bv;
        const size_t idx = ((size_t)b * NS + s) * ND + tid;
        const __nv_bfloat16 h = __float2bfloat16(o);
        Whi[idx] = h;
        Wlo[idx] = __float2bfloat16(o - __bfloat162float(h));
    }
}

// ---------------------------------------------------------------------------
// Read attention, emitting BC directly as bf16 hi/lo
// ---------------------------------------------------------------------------
__global__ void __launch_bounds__(512) attn_read_kernel(
    const float* __restrict__ Qr, const float* __restrict__ Kr,
    const float* __restrict__ Vr,
    __nv_bfloat16* __restrict__ Bhi, __nv_bfloat16* __restrict__ Blo)
{
    const int b = blockIdx.x;
    const int tid = threadIdx.x;
    __shared__ float sQr[NK][ND];
    __shared__ float sKr[NS][ND];
    __shared__ float sVr[NS][ND];
    __shared__ float sP[NK][NS];

    const float4* q4 = (const float4*)(Qr + (size_t)b * NK * ND);
    ((float4*)sQr)[tid]       = q4[tid];
    ((float4*)sQr)[tid + 512] = q4[tid + 512];
    ((float4*)sKr)[tid] = ((const float4*)(Kr + (size_t)b * NS * ND))[tid];
    ((float4*)sVr)[tid] = ((const float4*)(Vr + (size_t)b * NS * ND))[tid];
    __syncthreads();

    const int warp = tid >> 5, lane = tid & 31;
#pragma unroll
    for (int j = 0; j < 2; j++) {
        const int pair = warp * 2 + j;
        const int k = pair >> 2, s = pair & 3;
        float sum = 0.f;
#pragma unroll 4
        for (int i = lane; i < ND; i += 32) sum += sQr[k][i] * sKr[s][i];
#pragma unroll
        for (int o = 16; o; o >>= 1) sum += __shfl_xor_sync(0xffffffffu, sum, o);
        if (lane == 0) sP[k][s] = sum * ATT_SCALE;
    }
    __syncthreads();

    if (tid < NK) {
        const int k = tid;
        float mx = -INFINITY;
#pragma unroll
        for (int s = 0; s < NS; s++) mx = fmaxf(mx, sP[k][s]);
        float pv[NS], den = 0.f;
#pragma unroll
        for (int s = 0; s < NS; s++) { pv[s] = expf(sP[k][s] - mx); den += pv[s]; }
        const float inv = 1.f / den;
#pragma unroll
        for (int s = 0; s < NS; s++) sP[k][s] = pv[s] * inv;
    }
    __syncthreads();

#pragma unroll
    for (int k = 0; k < NK; k++) {
        float v = 0.f;
#pragma unroll
        for (int s = 0; s < NS; s++) v += sP[k][s] * sVr[s][tid];
        const size_t idx = ((size_t)b * NK + k) * ND + tid;
        const __nv_bfloat16 h = __float2bfloat16(v);
        Bhi[idx] = h;
        Blo[idx] = __float2bfloat16(v - __bfloat162float(h));
    }
}

// ---------------------------------------------------------------------------
// Final LN
// ---------------------------------------------------------------------------
__global__ void __launch_bounds__(512) ln_out_kernel(
    const float* __restrict__ hidden, const float* __restrict__ BCW,
    const float* __restrict__ g, const float* __restrict__ bb,
    float* __restrict__ out)
{
    const size_t r = blockIdx.x;
    const int tid = threadIdx.x;
    __shared__ float red[17];
    const float v = hidden[r * ND + tid] + BCW[r * ND + tid];
    const float mu = blk_sum512(v, red) * (1.f / 512.f);
    const float d = v - mu;
    const float var = blk_sum512(d * d, red) * (1.f / 512.f);
    out[r * ND + tid] = d * rsqrtf(var + LN_EPS) * g[tid] + bb[tid];
}

// ---------------------------------------------------------------------------
// launch
// ---------------------------------------------------------------------------
extern "C" void kernel_launch(void* const* d_in, const int* in_sizes, int n_in,
                              void* d_out, int out_size)
{
    const float*         hidden    = (const float*)d_in[0];
    const unsigned char* mask_raw  = (const unsigned char*)d_in[1];
    const float*         workspace = (const float*)d_in[2];
    const float*         Wq_w      = (const float*)d_in[3];
    const float*         Wk_w      = (const float*)d_in[4];
    const float*         Wv_w      = (const float*)d_in[5];
    const float*         Wq_r      = (const float*)d_in[6];
    const float*         Wk_r      = (const float*)d_in[7];
    const float*         Wv_r      = (const float*)d_in[8];
    const float*         Wo        = (const float*)d_in[9];
    const float*         g_ws      = (const float*)d_in[10];
    const float*         b_ws      = (const float*)d_in[11];
    const float*         g_out     = (const float*)d_in[12];
    const float*         b_out     = (const float*)d_in[13];
    float*               out       = (float*)d_out;

    float *pKw, *pVw, *pQr, *pKr, *pVr;
    cudaGetSymbolAddress((void**)&pKw,  sc_Kw);
    cudaGetSymbolAddress((void**)&pVw,  sc_Vw);
    cudaGetSymbolAddress((void**)&pQr,  sc_Qr);
    cudaGetSymbolAddress((void**)&pKr,  sc_Kr);
    cudaGetSymbolAddress((void**)&pVr,  sc_Vr);

    __nv_bfloat16 *hHi, *hLo, *xHi, *xLo, *wHi, *wLo;
    cudaGetSymbolAddress((void**)&hHi, sb_hHi);
    cudaGetSymbolAddress((void**)&hLo, sb_hLo);
    cudaGetSymbolAddress((void**)&xHi, sb_xHi);
    cudaGetSymbolAddress((void**)&xLo, sb_xLo);
    cudaGetSymbolAddress((void**)&wHi, sb_wHi);
    cudaGetSymbolAddress((void**)&wLo, sb_wLo);

    static int smem_set = 0;
    if (!smem_set) {
        cudaFuncSetAttribute(gemm512_mma,
                             cudaFuncAttributeMaxDynamicSharedMemorySize, GEMM_SMEM);
        smem_set = 1;
    }

    mask_canon_kernel<<<1, 1024>>>(mask_raw);
    qw_kernel<<<1, 512>>>(workspace, Wq_w);

    const int n4_big = NROWS * ND / 4;
    const int n4_w   = ND * ND / 4;
    const size_t WSZ = (size_t)ND * ND;

    split_kernel<<<(n4_big + 255) / 256, 256>>>(
        (const float4*)hidden, (__nv_bfloat162*)hHi, (__nv_bfloat162*)hLo, n4_big);

    const float* wsrc[6] = {Wk_w, Wv_w, Wq_r, Wk_r, Wv_r, Wo};
    for (int w = 0; w < 6; w++)
        split_kernel<<<(n4_w + 255) / 256, 256>>>(
            (const float4*)wsrc[w],
            (__nv_bfloat162*)(wHi + w * WSZ), (__nv_bfloat162*)(wLo + w * WSZ), n4_w);

    const dim3 gBig(4, NROWS / 128);   // (n-tiles, m-tiles)
    const dim3 gSml(4, NSROWS / 128);

    gemm512_mma<<<gBig, 256, GEMM_SMEM>>>(hHi, hLo, wHi + 0*WSZ, wLo + 0*WSZ, pKw);
    gemm512_mma<<<gBig, 256, GEMM_SMEM>>>(hHi, hLo, wHi + 1*WSZ, wLo + 1*WSZ, pVw);
    gemm512_mma<<<gBig, 256, GEMM_SMEM>>>(hHi, hLo, wHi + 2*WSZ, wLo + 2*WSZ, pQr);

    attn_write_kernel<<<NB, 512>>>(pKw, pVw, workspace, g_ws, b_ws, xHi, xLo);

    gemm512_mma<<<gSml, 256, GEMM_SMEM>>>(xHi, xLo, wHi + 3*WSZ, wLo + 3*WSZ, pKr);
    gemm512_mma<<<gSml, 256, GEMM_SMEM>>>(xHi, xLo, wHi + 4*WSZ, wLo + 4*WSZ, pVr);

    attn_read_kernel<<<NB, 512>>>(pQr, pKr, pVr, xHi, xLo);     // BC hi/lo

    gemm512_mma<<<gBig, 256, GEMM_SMEM>>>(xHi, xLo, wHi + 5*WSZ, wLo + 5*WSZ, pVw);

    ln_out_kernel<<<NROWS, 512>>>(hidden, pVw, g_out, b_out, out);
}